// round 11
// baseline (speedup 1.0000x reference)
#include <cuda_runtime.h>
#include <stdint.h>

#define WARPS_PER_BLOCK 4
#define NTHREADS (WARPS_PER_BLOCK * 32)
#define MINBLOCKS 5          // reg cap 65536/(128*5) = 102; 5 blocks/SM = 20 warps/SM

typedef unsigned long long ull;

__device__ __forceinline__ ull pack2(float lo, float hi) {
    ull r; asm("mov.b64 %0, {%1, %2};" : "=l"(r) : "f"(lo), "f"(hi)); return r;
}
__device__ __forceinline__ void unpack2(ull v, float& lo, float& hi) {
    asm("mov.b64 {%0, %1}, %2;" : "=f"(lo), "=f"(hi) : "l"(v));
}
__device__ __forceinline__ ull fma2(ull a, ull b, ull c) {
    ull d; asm("fma.rn.f32x2 %0, %1, %2, %3;" : "=l"(d) : "l"(a), "l"(b), "l"(c)); return d;
}
__device__ __forceinline__ ull add2(ull a, ull b) {
    ull d; asm("add.rn.f32x2 %0, %1, %2;" : "=l"(d) : "l"(a), "l"(b)); return d;
}

// ---------------- precomputed tables ----------------
__device__ uint32_t g_br_pos[60];
__device__ __align__(16) uint32_t g_c5_pos[120 * 16];    // transposed [o][ch]
__device__ __align__(16) float    g_f6wt[30 * 84 * 4];   // f6w tiled [j4][out][4]
__device__ __align__(16) float    g_rbfwt[21 * 10 * 4];  // rbfw tiled [j4][out][4]
__device__ __align__(16) ull      g_c1w2tmp[150];        // packed c1 weights (staging)
__device__ __align__(16) ull      g_c1b2tmp[6];          // packed c1 bias (staging)

__constant__ __align__(16) ull c_c1w2[150];              // lane-invariant -> ULDC port
__constant__ __align__(16) ull c_c1b2[6];

__global__ void prep_kernel(const float* __restrict__ w3,
                            const float* __restrict__ w4,
                            const float* __restrict__ w6,
                            const float* __restrict__ c5w,
                            const float* __restrict__ f6w,
                            const float* __restrict__ rbfw,
                            const float* __restrict__ c1w,
                            const float* __restrict__ c1b) {
    const int tid = blockIdx.x * blockDim.x + threadIdx.x;
    const int stride = blockDim.x * gridDim.x;
    if (tid < 60) {
        const float* wp;
        if (tid < 18)      wp = w3 + tid * 25;
        else if (tid < 54) wp = w4 + (tid - 18) * 25;
        else               wp = w6 + (tid - 54) * 25;
        uint32_t m = 0;
        for (int i = 0; i < 25; i++) if (wp[i] > 0.0f) m |= (1u << i);
        g_br_pos[tid] = m;
    }
    if (tid < 150) { float w = c1w[tid]; g_c1w2tmp[tid] = pack2(w, w); }
    if (tid < 6)   { float b = c1b[tid]; g_c1b2tmp[tid] = pack2(b, b); }
    for (int idx = tid; idx < 16 * 120; idx += stride) {
        int ch = idx / 120, o = idx % 120;
        const float* wp = c5w + o * 400 + ch * 25;
        uint32_t m = 0;
        for (int i = 0; i < 25; i++) if (wp[i] > 0.0f) m |= (1u << i);
        g_c5_pos[o * 16 + ch] = m;
    }
    for (int idx = tid; idx < 30 * 84 * 4; idx += stride) {
        int q = idx & 3, e = idx >> 2;
        int j4 = e / 84, i = e % 84;
        g_f6wt[idx] = f6w[i * 120 + j4 * 4 + q];
    }
    for (int idx = tid; idx < 21 * 10 * 4; idx += stride) {
        int q = idx & 3, e = idx >> 2;
        int j4 = e / 10, o = e % 10;
        g_rbfwt[idx] = rbfw[o * 84 + j4 * 4 + q];
    }
}

// ---------------- fused forward kernel ----------------
struct LateSmem {
    ull      sf2[120];
    ull      yv2[84];
    uint32_t b14[2 * 84];
    uint32_t pix[2 * 100];
    uint32_t cb[2 * 16];
};
struct __align__(16) WarpSmem {
    union {
        ull      xs2[32 * 32];     // packed tile, linear stride 32 ull (c1 phase only)
        LateSmem L;
    };
    uint8_t  posm8[2 * 6 * 28 * 8];// [s][ch][row][chunk-byte, low nibble = 4 col bits]
};
struct __align__(16) BlockSmem {
    WarpSmem w[WARPS_PER_BLOCK];
    uint32_t brpos[60];
    float    brb[16];
    float    c5b[120];
};

__global__ __launch_bounds__(NTHREADS, MINBLOCKS)
void lenet_kernel(const float* __restrict__ x,
                  const float* __restrict__ b3,   const float* __restrict__ b4,
                  const float* __restrict__ b6,   const float* __restrict__ c5b_g,
                  const float* __restrict__ f6b,
                  const float* __restrict__ rbfb,
                  float* __restrict__ out, int nsamples) {
    extern __shared__ unsigned char smem_raw[];
    BlockSmem& S = *reinterpret_cast<BlockSmem*>(smem_raw);

    const int tid = threadIdx.x;
    for (int i = tid; i < 60; i += NTHREADS)  S.brpos[i] = g_br_pos[i];
    for (int i = tid; i < 120; i += NTHREADS) S.c5b[i] = c5b_g[i];
    if (tid < 6)        S.brb[tid] = b3[tid];
    else if (tid < 15)  S.brb[tid] = b4[tid - 6];
    else if (tid == 15) S.brb[15]  = b6[0];
    __syncthreads();

    const int warp = tid >> 5, lane = tid & 31;
    const int sA = (blockIdx.x * WARPS_PER_BLOCK + warp) * 2;
    const int sAl = min(sA, nsamples - 1);
    const int sBl = min(sA + 1, nsamples - 1);
    WarpSmem& W = S.w[warp];

    // ---- load two x tiles, interleave into packed smem (linear layout) ----
    {
        const float4* xgA = reinterpret_cast<const float4*>(x + (size_t)sAl * 1024);
        const float4* xgB = reinterpret_cast<const float4*>(x + (size_t)sBl * 1024);
        for (int i = lane; i < 256; i += 32) {
            float4 a = xgA[i], b = xgB[i];
            ull* p = W.xs2 + i * 4;
            p[0] = pack2(a.x, b.x); p[1] = pack2(a.y, b.y);
            p[2] = pack2(a.z, b.z); p[3] = pack2(a.w, b.w);
        }
    }
    __syncwarp();

    // ---- c1: task = (row, 4-col chunk), ALL 6 channels; weights via constant (ULDC) ----
    // 196 real tasks; fixed 7 uniform iterations (uniform ctrl flow -> uniform const loads)
    #pragma unroll 1
    for (int it = 0; it < 7; it++) {
        const int t = it * 32 + lane;
        const bool valid = (t < 196);
        const int row = min(t / 7, 27);
        const int chunk = t % 7;
        ull acc[6][4];
        #pragma unroll
        for (int c = 0; c < 6; c++) {
            const ull b2 = c_c1b2[c];
            #pragma unroll
            for (int j = 0; j < 4; j++) acc[c][j] = b2;
        }
        const ull* xbase = W.xs2 + chunk * 4;
        #pragma unroll
        for (int dy = 0; dy < 5; dy++) {
            const ulonglong2* xr = reinterpret_cast<const ulonglong2*>(xbase + (row + dy) * 32);
            ulonglong2 x01 = xr[0], x23 = xr[1], x45 = xr[2], x67 = xr[3];
            const ull xv[8] = { x01.x, x01.y, x23.x, x23.y, x45.x, x45.y, x67.x, x67.y };
            #pragma unroll
            for (int c = 0; c < 6; c++) {
                #pragma unroll
                for (int k = 0; k < 5; k++) {
                    const ull w2 = c_c1w2[c * 25 + dy * 5 + k];   // compile-time const addr
                    #pragma unroll
                    for (int col = 0; col < 4; col++)
                        acc[c][col] = fma2(xv[col + k], w2, acc[c][col]);
                }
            }
        }
        if (valid) {
            #pragma unroll
            for (int c = 0; c < 6; c++) {
                uint32_t mA = 0, mB = 0;
                #pragma unroll
                for (int col = 0; col < 4; col++) {
                    float a, b; unpack2(acc[c][col], a, b);
                    if (a > 0.0f) mA |= (1u << col);
                    if (b > 0.0f) mB |= (1u << col);
                }
                const int base = c * 224 + row * 8 + chunk;
                W.posm8[base]        = (uint8_t)mA;
                W.posm8[1344 + base] = (uint8_t)mB;
            }
        }
    }
    __syncwarp();   // xs2 dead; W.L overlays it

    // ---- stage-1 relu+avgpool+sign: 8B row pair -> nibble compress -> 14-bit rows ----
    for (int v = lane; v < 168; v += 32) {
        const int s = (v >= 84) ? 1 : 0;
        const int u = s ? (v - 84) : v;
        const int ch = u / 14, pr = u % 14;
        const ull* pm = reinterpret_cast<const ull*>(W.posm8 + s * 1344 + ch * 224);
        ull vv = pm[2 * pr] | pm[2 * pr + 1];
        ull y = vv | (vv >> 4);                 // byte i = nib_i | nib_{i+1}<<4
        uint32_t m = __byte_perm((uint32_t)y, (uint32_t)(y >> 32), 0x6420) & 0x0FFFFFFFu;
        uint32_t c = (m | (m >> 1)) & 0x55555555u;
        c = (c | (c >> 1)) & 0x33333333u;
        c = (c | (c >> 2)) & 0x0F0F0F0Fu;
        c = (c | (c >> 4)) & 0x00FF00FFu;
        c = (c | (c >> 8)) & 0x0000FFFFu;
        W.L.b14[s * 84 + u] = c;
    }
    __syncwarp();

    // ---- 16 binary branch convs: column-strip tasks, branch-outer ----
    {
        const int I3[18] = {0,1,2, 1,2,3, 2,3,4, 3,4,5, 0,4,5, 0,1,5};
        const int I4[36] = {0,1,2,3, 1,2,3,4, 2,3,4,5, 0,3,4,5, 0,1,4,5,
                            0,1,2,5, 0,1,3,4, 1,2,4,5, 0,2,3,5};
        for (int t = lane; t < 60; t += 32) {
            const int s = (t >= 30) ? 1 : 0;
            const int u = s ? (t - 30) : t;
            const int col = u / 3, strip = u % 3;
            const int r0 = (strip == 0) ? 0 : (strip == 1 ? 4 : 7);
            const int nrows = (strip == 0) ? 4 : 3;
            const uint32_t* bp = W.L.b14 + s * 84;
            ull w64[6];
            #pragma unroll
            for (int ch = 0; ch < 6; ch++) {
                const uint32_t* rowp = bp + ch * 14 + r0;
                ull v = 0;
                #pragma unroll
                for (int q = 0; q < 7; q++)
                    v |= (ull)((rowp[q] >> col) & 31u) << (5 * q);
                if (nrows == 4) v |= (ull)((rowp[7] >> col) & 31u) << 35;
                w64[ch] = v;
            }
            uint32_t win[4][6]; int pc[4][6];
            #pragma unroll
            for (int i = 0; i < 4; i++) {
                #pragma unroll
                for (int ch = 0; ch < 6; ch++) {
                    uint32_t wv = (uint32_t)(w64[ch] >> (5 * i)) & 0x1FFFFFFu;
                    win[i][ch] = wv; pc[i][ch] = __popc(wv);
                }
            }
            uint32_t bits[4] = {0, 0, 0, 0};
            #pragma unroll
            for (int k = 0; k < 6; k++) {
                const int a = I3[3*k], b = I3[3*k+1], d = I3[3*k+2];
                const uint32_t m0 = S.brpos[3*k], m1 = S.brpos[3*k+1], m2 = S.brpos[3*k+2];
                const float bb = S.brb[k];
                #pragma unroll
                for (int i = 0; i < 4; i++) {
                    int sum = 2 * (__popc(win[i][a] & m0) + __popc(win[i][b] & m1)
                                 + __popc(win[i][d] & m2))
                              - (pc[i][a] + pc[i][b] + pc[i][d]);
                    if ((float)sum + bb > 0.0f) bits[i] |= (1u << k);
                }
            }
            #pragma unroll
            for (int k = 0; k < 9; k++) {
                const int a = I4[4*k], b = I4[4*k+1], d = I4[4*k+2], e = I4[4*k+3];
                const uint32_t m0 = S.brpos[18 + 4*k],     m1 = S.brpos[18 + 4*k + 1];
                const uint32_t m2 = S.brpos[18 + 4*k + 2], m3 = S.brpos[18 + 4*k + 3];
                const float bb = S.brb[6 + k];
                #pragma unroll
                for (int i = 0; i < 4; i++) {
                    int sum = 2 * (__popc(win[i][a] & m0) + __popc(win[i][b] & m1)
                                 + __popc(win[i][d] & m2) + __popc(win[i][e] & m3))
                              - (pc[i][a] + pc[i][b] + pc[i][d] + pc[i][e]);
                    if ((float)sum + bb > 0.0f) bits[i] |= (1u << (6 + k));
                }
            }
            {
                const float bb = S.brb[15];
                uint32_t m6[6];
                #pragma unroll
                for (int ch = 0; ch < 6; ch++) m6[ch] = S.brpos[54 + ch];
                #pragma unroll
                for (int i = 0; i < 4; i++) {
                    int sum = 0;
                    #pragma unroll
                    for (int ch = 0; ch < 6; ch++)
                        sum += 2 * __popc(win[i][ch] & m6[ch]) - pc[i][ch];
                    if ((float)sum + bb > 0.0f) bits[i] |= (1u << 15);
                }
            }
            uint32_t* pixp = W.L.pix + s * 100;
            #pragma unroll
            for (int i = 0; i < 4; i++)
                if (i < nrows) pixp[(r0 + i) * 10 + col] = bits[i];
        }
    }
    __syncwarp();

    // ---- stage-2 relu+pool+sign ----
    {
        const int s = lane >> 4, ch = lane & 15;
        const ull* pp2 = reinterpret_cast<const ull*>(W.L.pix + s * 100);
        uint32_t r = 0;
        #pragma unroll
        for (int u = 0; u < 25; u++) {
            const int pr = u / 5, pc2 = u % 5;
            ull pair = pp2[pr * 10 + pc2] | pp2[pr * 10 + 5 + pc2];
            uint32_t v = (uint32_t)pair | (uint32_t)(pair >> 32);
            r |= ((v >> ch) & 1u) << u;
        }
        W.L.cb[s * 16 + ch] = r;
    }
    __syncthreads();

    // ---- c5 (BLOCK-COOP) ----
    if (tid < 120) {
        const int o = tid;
        uint4 p[4];
        {
            const uint4* cp = reinterpret_cast<const uint4*>(g_c5_pos + o * 16);
            #pragma unroll
            for (int q = 0; q < 4; q++) p[q] = __ldg(cp + q);
        }
        const float b = S.c5b[o];
        #pragma unroll
        for (int w4 = 0; w4 < WARPS_PER_BLOCK; w4++) {
            uint32_t cbr[32];
            const uint4* cq = reinterpret_cast<const uint4*>(S.w[w4].L.cb);
            #pragma unroll
            for (int q = 0; q < 8; q++) {
                uint4 v = cq[q];
                cbr[4*q] = v.x; cbr[4*q+1] = v.y; cbr[4*q+2] = v.z; cbr[4*q+3] = v.w;
            }
            int tpA = 0, tpB = 0;
            #pragma unroll
            for (int ch = 0; ch < 16; ch++) { tpA += __popc(cbr[ch]); tpB += __popc(cbr[16 + ch]); }
            int aA = 0, aB = 0;
            #pragma unroll
            for (int q = 0; q < 4; q++) {
                aA += __popc(cbr[4*q] & p[q].x) + __popc(cbr[4*q+1] & p[q].y)
                    + __popc(cbr[4*q+2] & p[q].z) + __popc(cbr[4*q+3] & p[q].w);
                aB += __popc(cbr[16+4*q] & p[q].x) + __popc(cbr[16+4*q+1] & p[q].y)
                    + __popc(cbr[16+4*q+2] & p[q].z) + __popc(cbr[16+4*q+3] & p[q].w);
            }
            float vA = (float)(2 * aA - tpA) + b;
            float vB = (float)(2 * aB - tpB) + b;
            S.w[w4].L.sf2[o] = pack2(vA > 0.0f ? 1.0f : -1.0f, vB > 0.0f ? 1.0f : -1.0f);
        }
    }
    __syncthreads();

    // ---- f6 (BLOCK-COOP) ----
    if (tid < 84) {
        ull a0[WARPS_PER_BLOCK], a1[WARPS_PER_BLOCK];
        #pragma unroll
        for (int w4 = 0; w4 < WARPS_PER_BLOCK; w4++) { a0[w4] = 0; a1[w4] = 0; }
        const float4* wt = reinterpret_cast<const float4*>(g_f6wt) + tid;
        #pragma unroll 5
        for (int j4 = 0; j4 < 30; j4++) {
            float4 wv = __ldg(wt + j4 * 84);
            const ull wx = pack2(wv.x, wv.x), wy = pack2(wv.y, wv.y);
            const ull wz = pack2(wv.z, wv.z), ww = pack2(wv.w, wv.w);
            #pragma unroll
            for (int w4 = 0; w4 < WARPS_PER_BLOCK; w4++) {
                const ulonglong2* sp = reinterpret_cast<const ulonglong2*>(S.w[w4].L.sf2);
                ulonglong2 s01 = sp[2 * j4], s23 = sp[2 * j4 + 1];
                a0[w4] = fma2(s01.x, wx, a0[w4]);
                a1[w4] = fma2(s01.y, wy, a1[w4]);
                a0[w4] = fma2(s23.x, wz, a0[w4]);
                a1[w4] = fma2(s23.y, ww, a1[w4]);
            }
        }
        const float fb = __ldg(f6b + tid);
        #pragma unroll
        for (int w4 = 0; w4 < WARPS_PER_BLOCK; w4++) {
            float gA, gB; unpack2(add2(a0[w4], a1[w4]), gA, gB);
            S.w[w4].L.yv2[tid] = pack2(tanhf(1.7519f * (gA + fb)), tanhf(1.7519f * (gB + fb)));
        }
    }
    __syncthreads();

    // ---- rbf head (BLOCK-COOP) ----
    if (tid < 10 * WARPS_PER_BLOCK) {
        const int o = tid % 10, w4 = tid / 10;
        const int s0 = (blockIdx.x * WARPS_PER_BLOCK + w4) * 2;
        const float rb = __ldg(rbfb + o);
        ull a0 = pack2(rb, rb), a1 = 0;
        const ulonglong2* yp = reinterpret_cast<const ulonglong2*>(S.w[w4].L.yv2);
        const float4* wr = reinterpret_cast<const float4*>(g_rbfwt) + o;
        #pragma unroll 7
        for (int j4 = 0; j4 < 21; j4++) {
            float4 w = __ldg(wr + j4 * 10);
            ulonglong2 y01 = yp[2 * j4];
            ulonglong2 y23 = yp[2 * j4 + 1];
            a0 = fma2(y01.x, pack2(w.x, w.x), a0);
            a1 = fma2(y01.y, pack2(w.y, w.y), a1);
            a0 = fma2(y23.x, pack2(w.z, w.z), a0);
            a1 = fma2(y23.y, pack2(w.w, w.w), a1);
        }
        float oA, oB; unpack2(add2(a0, a1), oA, oB);
        if (s0 < nsamples)     out[(size_t)s0 * 10 + o]       = fmaxf(oA, 0.0f);
        if (s0 + 1 < nsamples) out[(size_t)(s0 + 1) * 10 + o] = fmaxf(oB, 0.0f);
    }
}

extern "C" void kernel_launch(void* const* d_in, const int* in_sizes, int n_in,
                              void* d_out, int out_size) {
    const float* x    = (const float*)d_in[0];
    const float* c1w  = (const float*)d_in[1];
    const float* c1b  = (const float*)d_in[2];
    const float* w3   = (const float*)d_in[3];
    const float* b3   = (const float*)d_in[4];
    const float* w4   = (const float*)d_in[5];
    const float* b4   = (const float*)d_in[6];
    const float* w6   = (const float*)d_in[7];
    const float* b6   = (const float*)d_in[8];
    const float* c5w  = (const float*)d_in[9];
    const float* c5b  = (const float*)d_in[10];
    const float* f6w  = (const float*)d_in[11];
    const float* f6b  = (const float*)d_in[12];
    const float* rbfw = (const float*)d_in[13];
    const float* rbfb = (const float*)d_in[14];
    float* out = (float*)d_out;

    const int nsamples = in_sizes[0] / 1024;
    const int smem_bytes = (int)sizeof(BlockSmem);

    prep_kernel<<<16, 256>>>(w3, w4, w6, c5w, f6w, rbfw, c1w, c1b);

    // stage packed c1 weights into constant memory (D2D memcpy nodes; graph-legal)
    void* srcw = nullptr; void* srcb = nullptr;
    cudaGetSymbolAddress(&srcw, g_c1w2tmp);
    cudaGetSymbolAddress(&srcb, g_c1b2tmp);
    cudaMemcpyToSymbolAsync(c_c1w2, srcw, 150 * sizeof(ull), 0, cudaMemcpyDeviceToDevice, 0);
    cudaMemcpyToSymbolAsync(c_c1b2, srcb, 6 * sizeof(ull), 0, cudaMemcpyDeviceToDevice, 0);

    cudaFuncSetAttribute(lenet_kernel, cudaFuncAttributeMaxDynamicSharedMemorySize, smem_bytes);
    const int samples_per_block = WARPS_PER_BLOCK * 2;
    const int blocks = (nsamples + samples_per_block - 1) / samples_per_block;
    lenet_kernel<<<blocks, NTHREADS, smem_bytes>>>(
        x, b3, b4, b6, c5b, f6b, rbfb, out, nsamples);
}

// round 12
// speedup vs baseline: 1.2771x; 1.2771x over previous
#include <cuda_runtime.h>
#include <stdint.h>

#define WARPS_PER_BLOCK 4
#define NTHREADS (WARPS_PER_BLOCK * 32)
#define MINBLOCKS 5          // reg cap 65536/(128*5) = 102; 5 blocks/SM = 20 warps/SM
#define XST 33               // xs2 row stride in packed elements

typedef unsigned long long ull;

__device__ __forceinline__ ull pack2(float lo, float hi) {
    ull r; asm("mov.b64 %0, {%1, %2};" : "=l"(r) : "f"(lo), "f"(hi)); return r;
}
__device__ __forceinline__ void unpack2(ull v, float& lo, float& hi) {
    asm("mov.b64 {%0, %1}, %2;" : "=f"(lo), "=f"(hi) : "l"(v));
}
__device__ __forceinline__ ull fma2(ull a, ull b, ull c) {
    ull d; asm("fma.rn.f32x2 %0, %1, %2, %3;" : "=l"(d) : "l"(a), "l"(b), "l"(c)); return d;
}
__device__ __forceinline__ ull add2(ull a, ull b) {
    ull d; asm("add.rn.f32x2 %0, %1, %2;" : "=l"(d) : "l"(a), "l"(b)); return d;
}

// ---------------- precomputed tables (written by prep kernel) ----------------
__device__ uint32_t g_br_pos[60];                        // 18 (w3) + 36 (w4) + 6 (w6)
__device__ __align__(16) uint32_t g_c5_pos[120 * 16];    // transposed [o][ch]
__device__ __align__(16) float    g_f6wt[30 * 84 * 4];   // f6w tiled [j4][out][4] (coalesced)
__device__ __align__(16) float    g_rbfwt[21 * 10 * 4];  // rbfw tiled [j4][out][4]

__global__ void prep_kernel(const float* __restrict__ w3,
                            const float* __restrict__ w4,
                            const float* __restrict__ w6,
                            const float* __restrict__ c5w,
                            const float* __restrict__ f6w,
                            const float* __restrict__ rbfw) {
    const int tid = blockIdx.x * blockDim.x + threadIdx.x;
    const int stride = blockDim.x * gridDim.x;
    if (tid < 60) {
        const float* wp;
        if (tid < 18)      wp = w3 + tid * 25;
        else if (tid < 54) wp = w4 + (tid - 18) * 25;
        else               wp = w6 + (tid - 54) * 25;
        uint32_t m = 0;
        for (int i = 0; i < 25; i++) if (wp[i] > 0.0f) m |= (1u << i);
        g_br_pos[tid] = m;
    }
    for (int idx = tid; idx < 16 * 120; idx += stride) {
        int ch = idx / 120, o = idx % 120;
        const float* wp = c5w + o * 400 + ch * 25;
        uint32_t m = 0;
        for (int i = 0; i < 25; i++) if (wp[i] > 0.0f) m |= (1u << i);
        g_c5_pos[o * 16 + ch] = m;
    }
    for (int idx = tid; idx < 30 * 84 * 4; idx += stride) {
        int q = idx & 3, e = idx >> 2;
        int j4 = e / 84, i = e % 84;
        g_f6wt[idx] = f6w[i * 120 + j4 * 4 + q];
    }
    for (int idx = tid; idx < 21 * 10 * 4; idx += stride) {
        int q = idx & 3, e = idx >> 2;
        int j4 = e / 10, o = e % 10;
        g_rbfwt[idx] = rbfw[o * 84 + j4 * 4 + q];
    }
}

// ---------------- fused forward kernel: one warp = TWO samples (f32x2 packed) ------------
struct LateSmem {
    ull      sf2[120];             // c5 outputs packed as +-1.0f pairs
    ull      yv2[84];              // f6 outputs packed
    uint32_t b14[2 * 6 * 16];      // pooled 14-bit rows, PADDED to 16 words/ch (vector loads)
    uint32_t pix[2 * 100];         // 16 branch bits per 10x10 pixel
    uint32_t cb[2 * 16];           // stage-2 pooled 25-bit words
};
struct __align__(16) WarpSmem {
    union {
        ull      xs2[32 * XST];    // packed (sampleA, sampleB) 32x32 tile (c1 phase only)
        LateSmem L;
    };
    uint8_t  posm8[2 * 6 * 28 * 4];// [s][ch][row][chunk] 7-bit chunk sign masks
};
struct __align__(16) BlockSmem {
    WarpSmem w[WARPS_PER_BLOCK];
    ull      c1w2v[6][5][6];       // weights [ch][dy][k(5)+pad] for LDS.128 broadcast
    ull      c1b2[8];
    uint32_t brpos[60];
    float    brb[16];
    float    c5b[120];
};

__global__ __launch_bounds__(NTHREADS, MINBLOCKS)
void lenet_kernel(const float* __restrict__ x,
                  const float* __restrict__ c1w_g, const float* __restrict__ c1b_g,
                  const float* __restrict__ b3,   const float* __restrict__ b4,
                  const float* __restrict__ b6,   const float* __restrict__ c5b_g,
                  const float* __restrict__ f6b,
                  const float* __restrict__ rbfb,
                  float* __restrict__ out, int nsamples) {
    extern __shared__ unsigned char smem_raw[];
    BlockSmem& S = *reinterpret_cast<BlockSmem*>(smem_raw);

    const int tid = threadIdx.x;
    for (int i = tid; i < 60; i += NTHREADS)  S.brpos[i] = g_br_pos[i];
    for (int i = tid; i < 150; i += NTHREADS) {
        const int ch = i / 25, r = i % 25;
        float w = c1w_g[i];
        S.c1w2v[ch][r / 5][r % 5] = pack2(w, w);
    }
    if (tid < 30) S.c1w2v[tid / 5][tid % 5][5] = 0;
    for (int i = tid; i < 120; i += NTHREADS) S.c5b[i] = c5b_g[i];
    if (tid < 6)        { float b = c1b_g[tid]; S.c1b2[tid] = pack2(b, b); }
    if (tid < 6)        S.brb[tid] = b3[tid];
    else if (tid < 15)  S.brb[tid] = b4[tid - 6];
    else if (tid == 15) S.brb[15]  = b6[0];
    __syncthreads();

    const int warp = tid >> 5, lane = tid & 31;
    const int sA = (blockIdx.x * WARPS_PER_BLOCK + warp) * 2;
    const int sAl = min(sA, nsamples - 1);
    const int sBl = min(sA + 1, nsamples - 1);
    WarpSmem& W = S.w[warp];

    // ---- load two x tiles, interleave into packed smem ----
    {
        const float4* xgA = reinterpret_cast<const float4*>(x + (size_t)sAl * 1024);
        const float4* xgB = reinterpret_cast<const float4*>(x + (size_t)sBl * 1024);
        for (int i = lane; i < 256; i += 32) {
            float4 a = xgA[i], b = xgB[i];
            int e = i * 4;
            ull* p = W.xs2 + (e >> 5) * XST + (e & 31);
            p[0] = pack2(a.x, b.x); p[1] = pack2(a.y, b.y);
            p[2] = pack2(a.z, b.z); p[3] = pack2(a.w, b.w);
        }
    }
    __syncwarp();

    // ---- c1: packed conv; task = (3-ch group, row, 7-col chunk); 224 tasks ----
    for (int t = lane; t < 224; t += 32) {
        const int g = (t >= 112) ? 1 : 0;
        const int rc = g ? (t - 112) : t;
        const int row = rc >> 2, chunk = rc & 3;
        const int ch0 = g * 3;
        ull acc[3][7];
        #pragma unroll
        for (int c = 0; c < 3; c++) {
            const ull b2 = S.c1b2[ch0 + c];
            #pragma unroll
            for (int j = 0; j < 7; j++) acc[c][j] = b2;
        }
        const ull* xbase = W.xs2 + chunk * 7;
        #pragma unroll
        for (int dy = 0; dy < 5; dy++) {
            const ull* xr = xbase + (row + dy) * XST;
            ull xv[11];
            #pragma unroll
            for (int j = 0; j < 11; j++) xv[j] = xr[j];
            #pragma unroll
            for (int c = 0; c < 3; c++) {
                const ulonglong2* wp = reinterpret_cast<const ulonglong2*>(S.c1w2v[ch0 + c][dy]);
                const ulonglong2 w01 = wp[0], w23 = wp[1], w45 = wp[2];
                const ull wk[5] = { w01.x, w01.y, w23.x, w23.y, w45.x };
                #pragma unroll
                for (int k = 0; k < 5; k++) {
                    #pragma unroll
                    for (int col = 0; col < 7; col++)
                        acc[c][col] = fma2(xv[col + k], wk[k], acc[c][col]);
                }
            }
        }
        #pragma unroll
        for (int c = 0; c < 3; c++) {
            uint32_t mA = 0, mB = 0;
            #pragma unroll
            for (int col = 0; col < 7; col++) {
                float a, b; unpack2(acc[c][col], a, b);
                if (a > 0.0f) mA |= (1u << col);
                if (b > 0.0f) mB |= (1u << col);
            }
            const int base = (ch0 + c) * 112 + row * 4 + chunk;
            W.posm8[base]       = (uint8_t)mA;
            W.posm8[672 + base] = (uint8_t)mB;
        }
    }
    __syncwarp();   // xs2 dead; W.L overlays it

    // ---- stage-1 relu+avgpool+sign: one LDS.64 per row-pair ----
    for (int v = lane; v < 168; v += 32) {
        const int s = (v >= 84) ? 1 : 0;
        const int u = s ? (v - 84) : v;
        const int ch = u / 14, pr = u % 14;
        const ull* pm64 = reinterpret_cast<const ull*>(W.posm8 + s * 672 + ch * 112);
        ull pair = pm64[pr];                       // rows 2pr (lo) and 2pr+1 (hi)
        uint32_t v32 = (uint32_t)pair | (uint32_t)(pair >> 32);
        uint32_t m = (v32 & 0x7Fu)
                   | (((v32 >> 8)  & 0x7Fu) << 7)
                   | (((v32 >> 16) & 0x7Fu) << 14)
                   | (((v32 >> 24) & 0x7Fu) << 21);
        uint32_t c = (m | (m >> 1)) & 0x55555555u;
        c = (c | (c >> 1)) & 0x33333333u;
        c = (c | (c >> 2)) & 0x0F0F0F0Fu;
        c = (c | (c >> 4)) & 0x00FF00FFu;
        c = (c | (c >> 8)) & 0x0000FFFFu;
        W.L.b14[(s * 6 + ch) * 16 + pr] = c;       // padded 16-word rows
    }
    __syncwarp();

    // ---- 16 binary branch convs: column-strip tasks; b14 rows via LDS.128 + SEL ----
    {
        const int I3[18] = {0,1,2, 1,2,3, 2,3,4, 3,4,5, 0,4,5, 0,1,5};
        const int I4[36] = {0,1,2,3, 1,2,3,4, 2,3,4,5, 0,3,4,5, 0,1,4,5,
                            0,1,2,5, 0,1,3,4, 1,2,4,5, 0,2,3,5};
        for (int t = lane; t < 60; t += 32) {
            const int s = (t >= 30) ? 1 : 0;
            const int u = s ? (t - 30) : t;
            const int col = u / 3, strip = u % 3;
            const int nrows = (strip == 0) ? 4 : 3;

            ull w64[6];
            #pragma unroll
            for (int ch = 0; ch < 6; ch++) {
                const uint4* rp = reinterpret_cast<const uint4*>(W.L.b14 + (s * 6 + ch) * 16);
                uint4 q0 = rp[0], q1 = rp[1], q2 = rp[2], q3 = rp[3];
                const uint32_t wv[15] = { q0.x, q0.y, q0.z, q0.w,
                                          q1.x, q1.y, q1.z, q1.w,
                                          q2.x, q2.y, q2.z, q2.w,
                                          q3.x, q3.y, q3.z };
                ull v = 0;
                #pragma unroll
                for (int q = 0; q < 7; q++) {
                    // row = r0 + q with r0 in {0,4,7}: select per strip (predicated SELs)
                    uint32_t rsel = (strip == 0) ? wv[q] : ((strip == 1) ? wv[4 + q] : wv[7 + q]);
                    v |= (ull)((rsel >> col) & 31u) << (5 * q);
                }
                if (nrows == 4) v |= (ull)((wv[7] >> col) & 31u) << 35;
                w64[ch] = v;
            }
            uint32_t win[4][6]; int pc[4][6];
            #pragma unroll
            for (int i = 0; i < 4; i++) {
                #pragma unroll
                for (int ch = 0; ch < 6; ch++) {
                    uint32_t wv = (uint32_t)(w64[ch] >> (5 * i)) & 0x1FFFFFFu;
                    win[i][ch] = wv; pc[i][ch] = __popc(wv);
                }
            }
            uint32_t bits[4] = {0, 0, 0, 0};
            #pragma unroll
            for (int k = 0; k < 6; k++) {
                const int a = I3[3*k], b = I3[3*k+1], d = I3[3*k+2];
                const uint32_t m0 = S.brpos[3*k], m1 = S.brpos[3*k+1], m2 = S.brpos[3*k+2];
                const float bb = S.brb[k];
                #pragma unroll
                for (int i = 0; i < 4; i++) {
                    int sum = 2 * (__popc(win[i][a] & m0) + __popc(win[i][b] & m1)
                                 + __popc(win[i][d] & m2))
                              - (pc[i][a] + pc[i][b] + pc[i][d]);
                    if ((float)sum + bb > 0.0f) bits[i] |= (1u << k);
                }
            }
            #pragma unroll
            for (int k = 0; k < 9; k++) {
                const int a = I4[4*k], b = I4[4*k+1], d = I4[4*k+2], e = I4[4*k+3];
                const uint32_t m0 = S.brpos[18 + 4*k],     m1 = S.brpos[18 + 4*k + 1];
                const uint32_t m2 = S.brpos[18 + 4*k + 2], m3 = S.brpos[18 + 4*k + 3];
                const float bb = S.brb[6 + k];
                #pragma unroll
                for (int i = 0; i < 4; i++) {
                    int sum = 2 * (__popc(win[i][a] & m0) + __popc(win[i][b] & m1)
                                 + __popc(win[i][d] & m2) + __popc(win[i][e] & m3))
                              - (pc[i][a] + pc[i][b] + pc[i][d] + pc[i][e]);
                    if ((float)sum + bb > 0.0f) bits[i] |= (1u << (6 + k));
                }
            }
            {
                const float bb = S.brb[15];
                uint32_t m6[6];
                #pragma unroll
                for (int ch = 0; ch < 6; ch++) m6[ch] = S.brpos[54 + ch];
                #pragma unroll
                for (int i = 0; i < 4; i++) {
                    int sum = 0;
                    #pragma unroll
                    for (int ch = 0; ch < 6; ch++)
                        sum += 2 * __popc(win[i][ch] & m6[ch]) - pc[i][ch];
                    if ((float)sum + bb > 0.0f) bits[i] |= (1u << 15);
                }
            }
            const int r0 = (strip == 0) ? 0 : (strip == 1 ? 4 : 7);
            uint32_t* pixp = W.L.pix + s * 100;
            #pragma unroll
            for (int i = 0; i < 4; i++)
                if (i < nrows) pixp[(r0 + i) * 10 + col] = bits[i];
        }
    }
    __syncwarp();

    // ---- stage-2 relu+pool+sign -> 400 bits per sample ----
    {
        const int s = lane >> 4, ch = lane & 15;
        const ull* pp2 = reinterpret_cast<const ull*>(W.L.pix + s * 100);
        uint32_t r = 0;
        #pragma unroll
        for (int u = 0; u < 25; u++) {
            const int pr = u / 5, pc2 = u % 5;
            ull pair = pp2[pr * 10 + pc2] | pp2[pr * 10 + 5 + pc2];
            uint32_t v = (uint32_t)pair | (uint32_t)(pair >> 32);
            r |= ((v >> ch) & 1u) << u;
        }
        W.L.cb[s * 16 + ch] = r;
    }
    __syncthreads();

    // ---- c5 (BLOCK-COOP): thread = output o ----
    if (tid < 120) {
        const int o = tid;
        uint4 p[4];
        {
            const uint4* cp = reinterpret_cast<const uint4*>(g_c5_pos + o * 16);
            #pragma unroll
            for (int q = 0; q < 4; q++) p[q] = __ldg(cp + q);
        }
        const float b = S.c5b[o];
        #pragma unroll
        for (int w4 = 0; w4 < WARPS_PER_BLOCK; w4++) {
            uint32_t cbr[32];
            const uint4* cq = reinterpret_cast<const uint4*>(S.w[w4].L.cb);
            #pragma unroll
            for (int q = 0; q < 8; q++) {
                uint4 v = cq[q];
                cbr[4*q] = v.x; cbr[4*q+1] = v.y; cbr[4*q+2] = v.z; cbr[4*q+3] = v.w;
            }
            int tpA = 0, tpB = 0;
            #pragma unroll
            for (int ch = 0; ch < 16; ch++) { tpA += __popc(cbr[ch]); tpB += __popc(cbr[16 + ch]); }
            int aA = 0, aB = 0;
            #pragma unroll
            for (int q = 0; q < 4; q++) {
                aA += __popc(cbr[4*q] & p[q].x) + __popc(cbr[4*q+1] & p[q].y)
                    + __popc(cbr[4*q+2] & p[q].z) + __popc(cbr[4*q+3] & p[q].w);
                aB += __popc(cbr[16+4*q] & p[q].x) + __popc(cbr[16+4*q+1] & p[q].y)
                    + __popc(cbr[16+4*q+2] & p[q].z) + __popc(cbr[16+4*q+3] & p[q].w);
            }
            float vA = (float)(2 * aA - tpA) + b;
            float vB = (float)(2 * aB - tpB) + b;
            S.w[w4].L.sf2[o] = pack2(vA > 0.0f ? 1.0f : -1.0f, vB > 0.0f ? 1.0f : -1.0f);
        }
    }
    __syncthreads();

    // ---- f6 (BLOCK-COOP, coalesced tiled weights): thread = output i ----
    if (tid < 84) {
        ull a0[WARPS_PER_BLOCK], a1[WARPS_PER_BLOCK];
        #pragma unroll
        for (int w4 = 0; w4 < WARPS_PER_BLOCK; w4++) { a0[w4] = 0; a1[w4] = 0; }
        const float4* wt = reinterpret_cast<const float4*>(g_f6wt) + tid;
        #pragma unroll 5
        for (int j4 = 0; j4 < 30; j4++) {
            float4 wv = __ldg(wt + j4 * 84);
            const ull wx = pack2(wv.x, wv.x), wy = pack2(wv.y, wv.y);
            const ull wz = pack2(wv.z, wv.z), ww = pack2(wv.w, wv.w);
            #pragma unroll
            for (int w4 = 0; w4 < WARPS_PER_BLOCK; w4++) {
                const ulonglong2* sp = reinterpret_cast<const ulonglong2*>(S.w[w4].L.sf2);
                ulonglong2 s01 = sp[2 * j4], s23 = sp[2 * j4 + 1];
                a0[w4] = fma2(s01.x, wx, a0[w4]);
                a1[w4] = fma2(s01.y, wy, a1[w4]);
                a0[w4] = fma2(s23.x, wz, a0[w4]);
                a1[w4] = fma2(s23.y, ww, a1[w4]);
            }
        }
        const float fb = __ldg(f6b + tid);
        #pragma unroll
        for (int w4 = 0; w4 < WARPS_PER_BLOCK; w4++) {
            float gA, gB; unpack2(add2(a0[w4], a1[w4]), gA, gB);
            S.w[w4].L.yv2[tid] = pack2(tanhf(1.7519f * (gA + fb)), tanhf(1.7519f * (gB + fb)));
        }
    }
    __syncthreads();

    // ---- rbf head (BLOCK-COOP): thread = (out o, warp-pair w4) ----
    if (tid < 10 * WARPS_PER_BLOCK) {
        const int o = tid % 10, w4 = tid / 10;
        const int s0 = (blockIdx.x * WARPS_PER_BLOCK + w4) * 2;
        const float rb = __ldg(rbfb + o);
        ull a0 = pack2(rb, rb), a1 = 0;
        const ulonglong2* yp = reinterpret_cast<const ulonglong2*>(S.w[w4].L.yv2);
        const float4* wr = reinterpret_cast<const float4*>(g_rbfwt) + o;
        #pragma unroll 7
        for (int j4 = 0; j4 < 21; j4++) {
            float4 w = __ldg(wr + j4 * 10);
            ulonglong2 y01 = yp[2 * j4];
            ulonglong2 y23 = yp[2 * j4 + 1];
            a0 = fma2(y01.x, pack2(w.x, w.x), a0);
            a1 = fma2(y01.y, pack2(w.y, w.y), a1);
            a0 = fma2(y23.x, pack2(w.z, w.z), a0);
            a1 = fma2(y23.y, pack2(w.w, w.w), a1);
        }
        float oA, oB; unpack2(add2(a0, a1), oA, oB);
        if (s0 < nsamples)     out[(size_t)s0 * 10 + o]       = fmaxf(oA, 0.0f);
        if (s0 + 1 < nsamples) out[(size_t)(s0 + 1) * 10 + o] = fmaxf(oB, 0.0f);
    }
}

extern "C" void kernel_launch(void* const* d_in, const int* in_sizes, int n_in,
                              void* d_out, int out_size) {
    const float* x    = (const float*)d_in[0];
    const float* c1w  = (const float*)d_in[1];
    const float* c1b  = (const float*)d_in[2];
    const float* w3   = (const float*)d_in[3];
    const float* b3   = (const float*)d_in[4];
    const float* w4   = (const float*)d_in[5];
    const float* b4   = (const float*)d_in[6];
    const float* w6   = (const float*)d_in[7];
    const float* b6   = (const float*)d_in[8];
    const float* c5w  = (const float*)d_in[9];
    const float* c5b  = (const float*)d_in[10];
    const float* f6w  = (const float*)d_in[11];
    const float* f6b  = (const float*)d_in[12];
    const float* rbfw = (const float*)d_in[13];
    const float* rbfb = (const float*)d_in[14];
    float* out = (float*)d_out;

    const int nsamples = in_sizes[0] / 1024;
    const int smem_bytes = (int)sizeof(BlockSmem);

    prep_kernel<<<16, 256>>>(w3, w4, w6, c5w, f6w, rbfw);

    cudaFuncSetAttribute(lenet_kernel, cudaFuncAttributeMaxDynamicSharedMemorySize, smem_bytes);
    const int samples_per_block = WARPS_PER_BLOCK * 2;
    const int blocks = (nsamples + samples_per_block - 1) / samples_per_block;
    lenet_kernel<<<blocks, NTHREADS, smem_bytes>>>(
        x, c1w, c1b, b3, b4, b6, c5b, f6b, rbfb, out, nsamples);
}

// round 13
// speedup vs baseline: 1.3220x; 1.0352x over previous
#include <cuda_runtime.h>
#include <stdint.h>

#define WARPS_PER_BLOCK 4
#define NTHREADS (WARPS_PER_BLOCK * 32)
#define MINBLOCKS 5          // reg cap 65536/(128*5) = 102; 5 blocks/SM = 20 warps/SM
#define XST 33               // xs2 row stride in packed elements

typedef unsigned long long ull;

__device__ __forceinline__ ull pack2(float lo, float hi) {
    ull r; asm("mov.b64 %0, {%1, %2};" : "=l"(r) : "f"(lo), "f"(hi)); return r;
}
__device__ __forceinline__ void unpack2(ull v, float& lo, float& hi) {
    asm("mov.b64 {%0, %1}, %2;" : "=f"(lo), "=f"(hi) : "l"(v));
}
__device__ __forceinline__ ull fma2(ull a, ull b, ull c) {
    ull d; asm("fma.rn.f32x2 %0, %1, %2, %3;" : "=l"(d) : "l"(a), "l"(b), "l"(c)); return d;
}
__device__ __forceinline__ ull add2(ull a, ull b) {
    ull d; asm("add.rn.f32x2 %0, %1, %2;" : "=l"(d) : "l"(a), "l"(b)); return d;
}

// ---------------- precomputed tables (written by prep kernel) ----------------
__device__ uint32_t g_br_pos[60];                        // 18 (w3) + 36 (w4) + 6 (w6)
__device__ __align__(16) uint32_t g_c5_pos[120 * 16];    // transposed [o][ch]
__device__ __align__(16) float    g_f6wt[30 * 84 * 4];   // f6w tiled [j4][out][4] (coalesced)
__device__ __align__(16) float    g_rbfwt[21 * 10 * 4];  // rbfw tiled [j4][out][4]

__global__ void prep_kernel(const float* __restrict__ w3,
                            const float* __restrict__ w4,
                            const float* __restrict__ w6,
                            const float* __restrict__ c5w,
                            const float* __restrict__ f6w,
                            const float* __restrict__ rbfw) {
    const int tid = blockIdx.x * blockDim.x + threadIdx.x;
    const int stride = blockDim.x * gridDim.x;
    if (tid < 60) {
        const float* wp;
        if (tid < 18)      wp = w3 + tid * 25;
        else if (tid < 54) wp = w4 + (tid - 18) * 25;
        else               wp = w6 + (tid - 54) * 25;
        uint32_t m = 0;
        for (int i = 0; i < 25; i++) if (wp[i] > 0.0f) m |= (1u << i);
        g_br_pos[tid] = m;
    }
    for (int idx = tid; idx < 16 * 120; idx += stride) {
        int ch = idx / 120, o = idx % 120;
        const float* wp = c5w + o * 400 + ch * 25;
        uint32_t m = 0;
        for (int i = 0; i < 25; i++) if (wp[i] > 0.0f) m |= (1u << i);
        g_c5_pos[o * 16 + ch] = m;
    }
    for (int idx = tid; idx < 30 * 84 * 4; idx += stride) {
        int q = idx & 3, e = idx >> 2;
        int j4 = e / 84, i = e % 84;
        g_f6wt[idx] = f6w[i * 120 + j4 * 4 + q];
    }
    for (int idx = tid; idx < 21 * 10 * 4; idx += stride) {
        int q = idx & 3, e = idx >> 2;
        int j4 = e / 10, o = e % 10;
        g_rbfwt[idx] = rbfw[o * 84 + j4 * 4 + q];
    }
}

// ---------------- fused forward kernel: one warp = TWO samples (f32x2 packed) ------------
struct LateSmem {
    ull      sf2[120];             // c5 outputs packed as +-1.0f pairs
    ull      yv2[84];              // f6 outputs packed
    uint32_t b14[2 * 84];          // pooled 14-bit rows
    uint32_t pix[2 * 100];         // 16 branch bits per 10x10 pixel
    uint32_t cb[2 * 16];           // stage-2 pooled 25-bit words
};
struct __align__(16) WarpSmem {
    union {
        ull      xs2[32 * XST];    // packed (sampleA, sampleB) 32x32 tile (c1 phase only)
        LateSmem L;
    };
    uint8_t  posm8[2 * 6 * 28 * 4];// [s][ch][row][chunk] 7-bit chunk sign masks
};
struct __align__(16) BlockSmem {
    WarpSmem w[WARPS_PER_BLOCK];
    ull      c1w2v[6][5][6];       // weights [ch][dy][k(5)+pad] for LDS.128 broadcast
    ull      c1b2[8];
    uint32_t brpos[60];
    float    brb[16];
    float    c5b[120];
};

__global__ __launch_bounds__(NTHREADS, MINBLOCKS)
void lenet_kernel(const float* __restrict__ x,
                  const float* __restrict__ c1w_g, const float* __restrict__ c1b_g,
                  const float* __restrict__ b3,   const float* __restrict__ b4,
                  const float* __restrict__ b6,   const float* __restrict__ c5b_g,
                  const float* __restrict__ f6b,
                  const float* __restrict__ rbfb,
                  float* __restrict__ out, int nsamples) {
    extern __shared__ unsigned char smem_raw[];
    BlockSmem& S = *reinterpret_cast<BlockSmem*>(smem_raw);

    const int tid = threadIdx.x;
    for (int i = tid; i < 60; i += NTHREADS)  S.brpos[i] = g_br_pos[i];
    for (int i = tid; i < 150; i += NTHREADS) {
        const int ch = i / 25, r = i % 25;
        float w = c1w_g[i];
        S.c1w2v[ch][r / 5][r % 5] = pack2(w, w);
    }
    if (tid < 30) S.c1w2v[tid / 5][tid % 5][5] = 0;
    for (int i = tid; i < 120; i += NTHREADS) S.c5b[i] = c5b_g[i];
    if (tid < 6)        { float b = c1b_g[tid]; S.c1b2[tid] = pack2(b, b); }
    if (tid < 6)        S.brb[tid] = b3[tid];
    else if (tid < 15)  S.brb[tid] = b4[tid - 6];
    else if (tid == 15) S.brb[15]  = b6[0];
    __syncthreads();

    const int warp = tid >> 5, lane = tid & 31;
    const int sA = (blockIdx.x * WARPS_PER_BLOCK + warp) * 2;
    const int sAl = min(sA, nsamples - 1);
    const int sBl = min(sA + 1, nsamples - 1);
    WarpSmem& W = S.w[warp];

    // ---- load two x tiles, interleave into packed smem ----
    {
        const float4* xgA = reinterpret_cast<const float4*>(x + (size_t)sAl * 1024);
        const float4* xgB = reinterpret_cast<const float4*>(x + (size_t)sBl * 1024);
        for (int i = lane; i < 256; i += 32) {
            float4 a = xgA[i], b = xgB[i];
            int e = i * 4;
            ull* p = W.xs2 + (e >> 5) * XST + (e & 31);
            p[0] = pack2(a.x, b.x); p[1] = pack2(a.y, b.y);
            p[2] = pack2(a.z, b.z); p[3] = pack2(a.w, b.w);
        }
    }
    __syncwarp();

    // ---- c1: packed conv; task = (3-ch group, row, 7-col chunk); 224 tasks ----
    for (int t = lane; t < 224; t += 32) {
        const int g = (t >= 112) ? 1 : 0;
        const int rc = g ? (t - 112) : t;
        const int row = rc >> 2, chunk = rc & 3;
        const int ch0 = g * 3;
        ull acc[3][7];
        #pragma unroll
        for (int c = 0; c < 3; c++) {
            const ull b2 = S.c1b2[ch0 + c];
            #pragma unroll
            for (int j = 0; j < 7; j++) acc[c][j] = b2;
        }
        const ull* xbase = W.xs2 + chunk * 7;
        #pragma unroll
        for (int dy = 0; dy < 5; dy++) {
            const ull* xr = xbase + (row + dy) * XST;
            ull xv[11];
            #pragma unroll
            for (int j = 0; j < 11; j++) xv[j] = xr[j];
            #pragma unroll
            for (int c = 0; c < 3; c++) {
                const ulonglong2* wp = reinterpret_cast<const ulonglong2*>(S.c1w2v[ch0 + c][dy]);
                const ulonglong2 w01 = wp[0], w23 = wp[1], w45 = wp[2];
                const ull wk[5] = { w01.x, w01.y, w23.x, w23.y, w45.x };
                #pragma unroll
                for (int k = 0; k < 5; k++) {
                    #pragma unroll
                    for (int col = 0; col < 7; col++)
                        acc[c][col] = fma2(xv[col + k], wk[k], acc[c][col]);
                }
            }
        }
        #pragma unroll
        for (int c = 0; c < 3; c++) {
            uint32_t mA = 0, mB = 0;
            #pragma unroll
            for (int col = 0; col < 7; col++) {
                float a, b; unpack2(acc[c][col], a, b);
                if (a > 0.0f) mA |= (1u << col);
                if (b > 0.0f) mB |= (1u << col);
            }
            const int base = (ch0 + c) * 112 + row * 4 + chunk;
            W.posm8[base]       = (uint8_t)mA;
            W.posm8[672 + base] = (uint8_t)mB;
        }
    }
    __syncwarp();   // xs2 dead; W.L overlays it

    // ---- stage-1 relu+avgpool+sign: one LDS.64 per row-pair ----
    for (int v = lane; v < 168; v += 32) {
        const int s = (v >= 84) ? 1 : 0;
        const int u = s ? (v - 84) : v;
        const int ch = u / 14, pr = u % 14;
        const ull* pm64 = reinterpret_cast<const ull*>(W.posm8 + s * 672 + ch * 112);
        ull pair = pm64[pr];                       // rows 2pr (lo word) and 2pr+1 (hi word)
        uint32_t v32 = (uint32_t)pair | (uint32_t)(pair >> 32);
        uint32_t m = (v32 & 0x7Fu)
                   | (((v32 >> 8)  & 0x7Fu) << 7)
                   | (((v32 >> 16) & 0x7Fu) << 14)
                   | (((v32 >> 24) & 0x7Fu) << 21);
        uint32_t c = (m | (m >> 1)) & 0x55555555u;
        c = (c | (c >> 1)) & 0x33333333u;
        c = (c | (c >> 2)) & 0x0F0F0F0Fu;
        c = (c | (c >> 4)) & 0x00FF00FFu;
        c = (c | (c >> 8)) & 0x0000FFFFu;
        W.L.b14[s * 84 + u] = c;
    }
    __syncwarp();

    // ---- 16 binary branch convs: column-strip tasks, branch-outer (R10 form) ----
    {
        const int I3[18] = {0,1,2, 1,2,3, 2,3,4, 3,4,5, 0,4,5, 0,1,5};
        const int I4[36] = {0,1,2,3, 1,2,3,4, 2,3,4,5, 0,3,4,5, 0,1,4,5,
                            0,1,2,5, 0,1,3,4, 1,2,4,5, 0,2,3,5};
        for (int t = lane; t < 60; t += 32) {
            const int s = (t >= 30) ? 1 : 0;
            const int u = s ? (t - 30) : t;
            const int col = u / 3, strip = u % 3;
            const int r0 = (strip == 0) ? 0 : (strip == 1 ? 4 : 7);
            const int nrows = (strip == 0) ? 4 : 3;
            const uint32_t* bp = W.L.b14 + s * 84;
            ull w64[6];
            #pragma unroll
            for (int ch = 0; ch < 6; ch++) {
                const uint32_t* rowp = bp + ch * 14 + r0;
                ull v = 0;
                #pragma unroll
                for (int q = 0; q < 7; q++)
                    v |= (ull)((rowp[q] >> col) & 31u) << (5 * q);
                if (nrows == 4) v |= (ull)((rowp[7] >> col) & 31u) << 35;
                w64[ch] = v;
            }
            uint32_t win[4][6]; int pc[4][6];
            #pragma unroll
            for (int i = 0; i < 4; i++) {
                #pragma unroll
                for (int ch = 0; ch < 6; ch++) {
                    uint32_t wv = (uint32_t)(w64[ch] >> (5 * i)) & 0x1FFFFFFu;
                    win[i][ch] = wv; pc[i][ch] = __popc(wv);
                }
            }
            uint32_t bits[4] = {0, 0, 0, 0};
            #pragma unroll
            for (int k = 0; k < 6; k++) {
                const int a = I3[3*k], b = I3[3*k+1], d = I3[3*k+2];
                const uint32_t m0 = S.brpos[3*k], m1 = S.brpos[3*k+1], m2 = S.brpos[3*k+2];
                const float bb = S.brb[k];
                #pragma unroll
                for (int i = 0; i < 4; i++) {
                    int sum = 2 * (__popc(win[i][a] & m0) + __popc(win[i][b] & m1)
                                 + __popc(win[i][d] & m2))
                              - (pc[i][a] + pc[i][b] + pc[i][d]);
                    if ((float)sum + bb > 0.0f) bits[i] |= (1u << k);
                }
            }
            #pragma unroll
            for (int k = 0; k < 9; k++) {
                const int a = I4[4*k], b = I4[4*k+1], d = I4[4*k+2], e = I4[4*k+3];
                const uint32_t m0 = S.brpos[18 + 4*k],     m1 = S.brpos[18 + 4*k + 1];
                const uint32_t m2 = S.brpos[18 + 4*k + 2], m3 = S.brpos[18 + 4*k + 3];
                const float bb = S.brb[6 + k];
                #pragma unroll
                for (int i = 0; i < 4; i++) {
                    int sum = 2 * (__popc(win[i][a] & m0) + __popc(win[i][b] & m1)
                                 + __popc(win[i][d] & m2) + __popc(win[i][e] & m3))
                              - (pc[i][a] + pc[i][b] + pc[i][d] + pc[i][e]);
                    if ((float)sum + bb > 0.0f) bits[i] |= (1u << (6 + k));
                }
            }
            {
                const float bb = S.brb[15];
                uint32_t m6[6];
                #pragma unroll
                for (int ch = 0; ch < 6; ch++) m6[ch] = S.brpos[54 + ch];
                #pragma unroll
                for (int i = 0; i < 4; i++) {
                    int sum = 0;
                    #pragma unroll
                    for (int ch = 0; ch < 6; ch++)
                        sum += 2 * __popc(win[i][ch] & m6[ch]) - pc[i][ch];
                    if ((float)sum + bb > 0.0f) bits[i] |= (1u << 15);
                }
            }
            uint32_t* pixp = W.L.pix + s * 100;
            #pragma unroll
            for (int i = 0; i < 4; i++)
                if (i < nrows) pixp[(r0 + i) * 10 + col] = bits[i];
        }
    }
    __syncwarp();

    // ---- stage-2 relu+pool+sign -> 400 bits per sample ----
    {
        const int s = lane >> 4, ch = lane & 15;
        const ull* pp2 = reinterpret_cast<const ull*>(W.L.pix + s * 100);
        uint32_t r = 0;
        #pragma unroll
        for (int u = 0; u < 25; u++) {
            const int pr = u / 5, pc2 = u % 5;
            ull pair = pp2[pr * 10 + pc2] | pp2[pr * 10 + 5 + pc2];
            uint32_t v = (uint32_t)pair | (uint32_t)(pair >> 32);
            r |= ((v >> ch) & 1u) << u;
        }
        W.L.cb[s * 16 + ch] = r;
    }
    __syncthreads();

    // ---- c5 (BLOCK-COOP): thread = output o ----
    if (tid < 120) {
        const int o = tid;
        uint4 p[4];
        {
            const uint4* cp = reinterpret_cast<const uint4*>(g_c5_pos + o * 16);
            #pragma unroll
            for (int q = 0; q < 4; q++) p[q] = __ldg(cp + q);
        }
        const float b = S.c5b[o];
        #pragma unroll
        for (int w4 = 0; w4 < WARPS_PER_BLOCK; w4++) {
            uint32_t cbr[32];
            const uint4* cq = reinterpret_cast<const uint4*>(S.w[w4].L.cb);
            #pragma unroll
            for (int q = 0; q < 8; q++) {
                uint4 v = cq[q];
                cbr[4*q] = v.x; cbr[4*q+1] = v.y; cbr[4*q+2] = v.z; cbr[4*q+3] = v.w;
            }
            int tpA = 0, tpB = 0;
            #pragma unroll
            for (int ch = 0; ch < 16; ch++) { tpA += __popc(cbr[ch]); tpB += __popc(cbr[16 + ch]); }
            int aA = 0, aB = 0;
            #pragma unroll
            for (int q = 0; q < 4; q++) {
                aA += __popc(cbr[4*q] & p[q].x) + __popc(cbr[4*q+1] & p[q].y)
                    + __popc(cbr[4*q+2] & p[q].z) + __popc(cbr[4*q+3] & p[q].w);
                aB += __popc(cbr[16+4*q] & p[q].x) + __popc(cbr[16+4*q+1] & p[q].y)
                    + __popc(cbr[16+4*q+2] & p[q].z) + __popc(cbr[16+4*q+3] & p[q].w);
            }
            float vA = (float)(2 * aA - tpA) + b;
            float vB = (float)(2 * aB - tpB) + b;
            S.w[w4].L.sf2[o] = pack2(vA > 0.0f ? 1.0f : -1.0f, vB > 0.0f ? 1.0f : -1.0f);
        }
    }
    __syncthreads();

    // ---- f6 (BLOCK-COOP, coalesced tiled weights): thread = output i ----
    if (tid < 84) {
        ull a0[WARPS_PER_BLOCK], a1[WARPS_PER_BLOCK];
        #pragma unroll
        for (int w4 = 0; w4 < WARPS_PER_BLOCK; w4++) { a0[w4] = 0; a1[w4] = 0; }
        const float4* wt = reinterpret_cast<const float4*>(g_f6wt) + tid;
        #pragma unroll 5
        for (int j4 = 0; j4 < 30; j4++) {
            float4 wv = __ldg(wt + j4 * 84);
            const ull wx = pack2(wv.x, wv.x), wy = pack2(wv.y, wv.y);
            const ull wz = pack2(wv.z, wv.z), ww = pack2(wv.w, wv.w);
            #pragma unroll
            for (int w4 = 0; w4 < WARPS_PER_BLOCK; w4++) {
                const ulonglong2* sp = reinterpret_cast<const ulonglong2*>(S.w[w4].L.sf2);
                ulonglong2 s01 = sp[2 * j4], s23 = sp[2 * j4 + 1];
                a0[w4] = fma2(s01.x, wx, a0[w4]);
                a1[w4] = fma2(s01.y, wy, a1[w4]);
                a0[w4] = fma2(s23.x, wz, a0[w4]);
                a1[w4] = fma2(s23.y, ww, a1[w4]);
            }
        }
        const float fb = __ldg(f6b + tid);
        #pragma unroll
        for (int w4 = 0; w4 < WARPS_PER_BLOCK; w4++) {
            float gA, gB; unpack2(add2(a0[w4], a1[w4]), gA, gB);
            S.w[w4].L.yv2[tid] = pack2(tanhf(1.7519f * (gA + fb)), tanhf(1.7519f * (gB + fb)));
        }
    }
    __syncthreads();

    // ---- rbf head (BLOCK-COOP): thread = (out o, warp-pair w4) ----
    if (tid < 10 * WARPS_PER_BLOCK) {
        const int o = tid % 10, w4 = tid / 10;
        const int s0 = (blockIdx.x * WARPS_PER_BLOCK + w4) * 2;
        const float rb = __ldg(rbfb + o);
        ull a0 = pack2(rb, rb), a1 = 0;
        const ulonglong2* yp = reinterpret_cast<const ulonglong2*>(S.w[w4].L.yv2);
        const float4* wr = reinterpret_cast<const float4*>(g_rbfwt) + o;
        #pragma unroll 7
        for (int j4 = 0; j4 < 21; j4++) {
            float4 w = __ldg(wr + j4 * 10);
            ulonglong2 y01 = yp[2 * j4];
            ulonglong2 y23 = yp[2 * j4 + 1];
            a0 = fma2(y01.x, pack2(w.x, w.x), a0);
            a1 = fma2(y01.y, pack2(w.y, w.y), a1);
            a0 = fma2(y23.x, pack2(w.z, w.z), a0);
            a1 = fma2(y23.y, pack2(w.w, w.w), a1);
        }
        float oA, oB; unpack2(add2(a0, a1), oA, oB);
        if (s0 < nsamples)     out[(size_t)s0 * 10 + o]       = fmaxf(oA, 0.0f);
        if (s0 + 1 < nsamples) out[(size_t)(s0 + 1) * 10 + o] = fmaxf(oB, 0.0f);
    }
}

extern "C" void kernel_launch(void* const* d_in, const int* in_sizes, int n_in,
                              void* d_out, int out_size) {
    const float* x    = (const float*)d_in[0];
    const float* c1w  = (const float*)d_in[1];
    const float* c1b  = (const float*)d_in[2];
    const float* w3   = (const float*)d_in[3];
    const float* b3   = (const float*)d_in[4];
    const float* w4   = (const float*)d_in[5];
    const float* b4   = (const float*)d_in[6];
    const float* w6   = (const float*)d_in[7];
    const float* b6   = (const float*)d_in[8];
    const float* c5w  = (const float*)d_in[9];
    const float* c5b  = (const float*)d_in[10];
    const float* f6w  = (const float*)d_in[11];
    const float* f6b  = (const float*)d_in[12];
    const float* rbfw = (const float*)d_in[13];
    const float* rbfb = (const float*)d_in[14];
    float* out = (float*)d_out;

    const int nsamples = in_sizes[0] / 1024;
    const int smem_bytes = (int)sizeof(BlockSmem);

    prep_kernel<<<16, 256>>>(w3, w4, w6, c5w, f6w, rbfw);

    cudaFuncSetAttribute(lenet_kernel, cudaFuncAttributeMaxDynamicSharedMemorySize, smem_bytes);
    const int samples_per_block = WARPS_PER_BLOCK * 2;
    const int blocks = (nsamples + samples_per_block - 1) / samples_per_block;
    lenet_kernel<<<blocks, NTHREADS, smem_bytes>>>(
        x, c1w, c1b, b3, b4, b6, c5b, f6b, rbfb, out, nsamples);
}